// round 3
// baseline (speedup 1.0000x reference)
#include <cuda_runtime.h>
#include <cstdint>

#define NPTS 30000
#define CDIM 128
#define HEADS 8
#define DHEAD 16
#define SNBR 16
#define OSDIM 16
#define EPSV 1e-5f

// Scratch for Q/K/V projections (device globals: no allocation allowed)
__device__ float g_xq[NPTS * CDIM];
__device__ float g_xk[NPTS * CDIM];
__device__ float g_xv[NPTS * CDIM];

// ---------------------------------------------------------------------------
// Kernel 1: fused QKV GEMM.  grid = (ceil(N/128), 3), block = 256.
// 128x128 output tile per block, 8x8 micro-tile per thread, K-step 8.
// ---------------------------------------------------------------------------
__global__ __launch_bounds__(256, 2)
void qkv_gemm(const float* __restrict__ x,
              const float* __restrict__ Wq, const float* __restrict__ bq,
              const float* __restrict__ Wk, const float* __restrict__ bk,
              const float* __restrict__ Wv, const float* __restrict__ bv)
{
    const float* W;
    const float* bias;
    float* dst;
    if (blockIdx.y == 0)      { W = Wq; bias = bq; dst = g_xq; }
    else if (blockIdx.y == 1) { W = Wk; bias = bk; dst = g_xk; }
    else                      { W = Wv; bias = bv; dst = g_xv; }

    __shared__ __align__(16) float As[8][132];   // As[k][m]  (padded: conflict-free writes)
    __shared__ __align__(16) float Bs[8][132];   // Bs[k][n]

    const int t   = threadIdx.x;         // 0..255
    const int tx  = t & 15;              // col group
    const int ty  = t >> 4;              // row group
    const int row0 = blockIdx.x * 128;

    float acc[8][8];
#pragma unroll
    for (int i = 0; i < 8; i++)
#pragma unroll
        for (int j = 0; j < 8; j++) acc[i][j] = 0.f;

    for (int kk = 0; kk < CDIM; kk += 8) {
        // Load A tile (x rows): 1024 elems, 4 per thread. 8 threads per row,
        // each 32B row-chunk is one full sector.
#pragma unroll
        for (int r = 0; r < 4; r++) {
            int q = t + r * 256;
            int m = q >> 3;
            int k = q & 7;
            int gr = row0 + m;
            As[k][m] = (gr < NPTS) ? x[gr * CDIM + kk + k] : 0.f;
        }
        // Load B tile (weights): coalesced rows.
#pragma unroll
        for (int r = 0; r < 4; r++) {
            int q = t + r * 256;
            int k = q >> 7;
            int n = q & 127;
            Bs[k][n] = W[(kk + k) * CDIM + n];
        }
        __syncthreads();

#pragma unroll
        for (int k = 0; k < 8; k++) {
            float4 a0 = *(const float4*)&As[k][ty * 8];
            float4 a1 = *(const float4*)&As[k][ty * 8 + 4];
            float4 b0 = *(const float4*)&Bs[k][tx * 8];
            float4 b1 = *(const float4*)&Bs[k][tx * 8 + 4];
            float a[8] = {a0.x, a0.y, a0.z, a0.w, a1.x, a1.y, a1.z, a1.w};
            float b[8] = {b0.x, b0.y, b0.z, b0.w, b1.x, b1.y, b1.z, b1.w};
#pragma unroll
            for (int i = 0; i < 8; i++)
#pragma unroll
                for (int j = 0; j < 8; j++)
                    acc[i][j] += a[i] * b[j];
        }
        __syncthreads();
    }

    // Epilogue: add bias, store (float4).
    float bj[8];
#pragma unroll
    for (int j = 0; j < 8; j++) bj[j] = bias[tx * 8 + j];

#pragma unroll
    for (int i = 0; i < 8; i++) {
        int gr = row0 + ty * 8 + i;
        if (gr < NPTS) {
            float4 o0, o1;
            o0.x = acc[i][0] + bj[0]; o0.y = acc[i][1] + bj[1];
            o0.z = acc[i][2] + bj[2]; o0.w = acc[i][3] + bj[3];
            o1.x = acc[i][4] + bj[4]; o1.y = acc[i][5] + bj[5];
            o1.z = acc[i][6] + bj[6]; o1.w = acc[i][7] + bj[7];
            *(float4*)&dst[gr * CDIM + tx * 8]     = o0;
            *(float4*)&dst[gr * CDIM + tx * 8 + 4] = o1;
        }
    }
}

// ---------------------------------------------------------------------------
// Kernel 2: per-point fused attention. One block (128 threads) per point.
// tid = h*16 + s  ->  softmax over s = 16-lane shfl butterfly inside half-warp
// ---------------------------------------------------------------------------
__global__ __launch_bounds__(128)
void attn_kernel(const float* __restrict__ p,
                 const int*   __restrict__ idx,
                 const float* __restrict__ Wp1, const float* __restrict__ bp1,
                 const float* __restrict__ gp,  const float* __restrict__ betap,
                 const float* __restrict__ Wp2, const float* __restrict__ bp2,
                 const float* __restrict__ gw1, const float* __restrict__ betaw1,
                 const float* __restrict__ Ww1, const float* __restrict__ bw1,
                 const float* __restrict__ gw2, const float* __restrict__ betaw2,
                 const float* __restrict__ Ww2, const float* __restrict__ bw2,
                 float* __restrict__ out)
{
    const int i   = blockIdx.x;
    const int tid = threadIdx.x;          // 0..127

    __shared__ __align__(16) float skT[CDIM][SNBR + 1];   // transposed K gather
    __shared__ __align__(16) float svT[CDIM][SNBR + 1];   // transposed V gather
    __shared__ __align__(16) float sxq[CDIM];
    __shared__ __align__(16) float swp2[3 * CDIM];
    __shared__ __align__(16) float sbp2[CDIM];
    __shared__ __align__(16) float sW1[DHEAD * OSDIM];
    __shared__ __align__(16) float sbw1[OSDIM], sgw1[DHEAD], sbetaw1[DHEAD];
    __shared__ __align__(16) float sgw2[OSDIM], sbetaw2[OSDIM], srs2[OSDIM];
    __shared__ __align__(16) float sout[CDIM];
    __shared__ float sbw2sum;
    __shared__ int   sidx[SNBR];

    // --- stage block-constant data ---
    if (tid < SNBR) sidx[tid] = idx[i * SNBR + tid];
    sxq[tid]        = g_xq[i * CDIM + tid];
    swp2[tid]       = Wp2[tid];
    swp2[128 + tid] = Wp2[128 + tid];
    swp2[256 + tid] = Wp2[256 + tid];
    sbp2[tid]       = bp2[tid];
    if (tid < 128) { /* always true */ }
    sW1[tid]        = Ww1[tid];
    sW1[128 + tid]  = Ww1[128 + tid];
    if (tid < OSDIM) {
        float rs = 0.f;
#pragma unroll
        for (int o = 0; o < OSDIM; o++) rs += Ww2[tid * OSDIM + o];
        srs2[tid]    = rs;
        sbw1[tid]    = bw1[tid];
        sgw1[tid]    = gw1[tid];
        sbetaw1[tid] = betaw1[tid];
        sgw2[tid]    = gw2[tid];
        sbetaw2[tid] = betaw2[tid];
    }
    if (tid == 0) {
        float sb = 0.f;
#pragma unroll
        for (int o = 0; o < OSDIM; o++) sb += bw2[o];
        sbw2sum = sb;
    }
    __syncthreads();

    // --- gather k/v rows (coalesced, transposed into smem) ---
    {
        const int warp = tid >> 5;
        const int lane = tid & 31;
#pragma unroll
        for (int j = 0; j < 4; j++) {
            int s   = warp * 4 + j;
            int row = sidx[s];
            float4 k4 = *(const float4*)(g_xk + (size_t)row * CDIM + lane * 4);
            float4 v4 = *(const float4*)(g_xv + (size_t)row * CDIM + lane * 4);
            int c = lane * 4;
            skT[c + 0][s] = k4.x; skT[c + 1][s] = k4.y;
            skT[c + 2][s] = k4.z; skT[c + 3][s] = k4.w;
            svT[c + 0][s] = v4.x; svT[c + 1][s] = v4.y;
            svT[c + 2][s] = v4.z; svT[c + 3][s] = v4.w;
        }
    }
    __syncthreads();

    const int s    = tid & 15;      // neighbor
    const int h    = tid >> 4;      // head
    const int base = h * DHEAD;

    // --- positional encoding for (i, s) ---
    const int nrow = sidx[s];
    float pr0 = p[nrow * 3 + 0] - p[i * 3 + 0];
    float pr1 = p[nrow * 3 + 1] - p[i * 3 + 1];
    float pr2 = p[nrow * 3 + 2] - p[i * 3 + 2];

    float t0 = pr0 * Wp1[0] + pr1 * Wp1[3] + pr2 * Wp1[6] + bp1[0];
    float t1 = pr0 * Wp1[1] + pr1 * Wp1[4] + pr2 * Wp1[7] + bp1[1];
    float t2 = pr0 * Wp1[2] + pr1 * Wp1[5] + pr2 * Wp1[8] + bp1[2];

    float m3 = (t0 + t1 + t2) * (1.f / 3.f);
    float d0 = t0 - m3, d1 = t1 - m3, d2 = t2 - m3;
    float v3 = (d0 * d0 + d1 * d1 + d2 * d2) * (1.f / 3.f);
    float rstd3 = rsqrtf(v3 + EPSV);
    float a0 = fmaxf(d0 * rstd3 * gp[0] + betap[0], 0.f);
    float a1 = fmaxf(d1 * rstd3 * gp[1] + betap[1], 0.f);
    float a2 = fmaxf(d2 * rstd3 * gp[2] + betap[2], 0.f);

    // --- r = k + pe - q ;  ve = v + pe ---
    float r[DHEAD], ve[DHEAD];
#pragma unroll
    for (int d = 0; d < DHEAD; d++) {
        float pev = a0 * swp2[base + d]
                  + a1 * swp2[128 + base + d]
                  + a2 * swp2[256 + base + d]
                  + sbp2[base + d];
        r[d]  = skT[base + d][s] + pev - sxq[base + d];
        ve[d] = svT[base + d][s] + pev;
    }

    // --- LN over D, relu ---
    {
        float mean = 0.f;
#pragma unroll
        for (int d = 0; d < DHEAD; d++) mean += r[d];
        mean *= (1.f / DHEAD);
        float var = 0.f;
#pragma unroll
        for (int d = 0; d < DHEAD; d++) { float dd = r[d] - mean; var += dd * dd; }
        var *= (1.f / DHEAD);
        float rstd = rsqrtf(var + EPSV);
#pragma unroll
        for (int d = 0; d < DHEAD; d++)
            r[d] = fmaxf((r[d] - mean) * rstd * sgw1[d] + sbetaw1[d], 0.f);
    }

    // --- w1 = relu_ln(r) @ Ww1 + bw1 ---
    float w1[OSDIM];
#pragma unroll
    for (int o = 0; o < OSDIM; o++) w1[o] = sbw1[o];
#pragma unroll
    for (int d = 0; d < DHEAD; d++) {
        float ud = r[d];
#pragma unroll
        for (int o4 = 0; o4 < OSDIM; o4 += 4) {
            float4 wv = *(const float4*)&sW1[d * OSDIM + o4];
            w1[o4 + 0] += ud * wv.x;
            w1[o4 + 1] += ud * wv.y;
            w1[o4 + 2] += ud * wv.z;
            w1[o4 + 3] += ud * wv.w;
        }
    }

    // --- LN over OS, relu ---
    {
        float mean = 0.f;
#pragma unroll
        for (int o = 0; o < OSDIM; o++) mean += w1[o];
        mean *= (1.f / OSDIM);
        float var = 0.f;
#pragma unroll
        for (int o = 0; o < OSDIM; o++) { float dd = w1[o] - mean; var += dd * dd; }
        var *= (1.f / OSDIM);
        float rstd = rsqrtf(var + EPSV);
#pragma unroll
        for (int o = 0; o < OSDIM; o++)
            w1[o] = fmaxf((w1[o] - mean) * rstd * sgw2[o] + sbetaw2[o], 0.f);
    }

    // --- logit = mean over OS of (y @ Ww2 + bw2) = y @ rowsum(Ww2)/16 + mean(bw2)
    float logit = sbw2sum;
#pragma unroll
    for (int o = 0; o < OSDIM; o++) logit += w1[o] * srs2[o];
    logit *= (1.f / OSDIM);

    // --- softmax over s (16-lane butterfly inside half-warp) ---
    float mx = logit;
#pragma unroll
    for (int j = 8; j >= 1; j >>= 1)
        mx = fmaxf(mx, __shfl_xor_sync(0xffffffffu, mx, j));
    float e = expf(logit - mx);
    float se = e;
#pragma unroll
    for (int j = 8; j >= 1; j >>= 1)
        se += __shfl_xor_sync(0xffffffffu, se, j);
    float w = e / se;

    // --- weighted sum over s ---
#pragma unroll
    for (int d = 0; d < DHEAD; d++) ve[d] *= w;
#pragma unroll
    for (int j = 8; j >= 1; j >>= 1)
#pragma unroll
        for (int d = 0; d < DHEAD; d++)
            ve[d] += __shfl_xor_sync(0xffffffffu, ve[d], j);

    if (s == 0) {
#pragma unroll
        for (int d = 0; d < DHEAD; d++) sout[base + d] = ve[d];
    }
    __syncthreads();

    out[(size_t)i * CDIM + tid] = sout[tid];
}

// ---------------------------------------------------------------------------
// Launch
// ---------------------------------------------------------------------------
extern "C" void kernel_launch(void* const* d_in, const int* in_sizes, int n_in,
                              void* d_out, int out_size)
{
    const float* p      = (const float*)d_in[0];
    const float* x      = (const float*)d_in[1];
    const int*   idx    = (const int*)  d_in[2];
    const float* Wq     = (const float*)d_in[3];
    const float* bq     = (const float*)d_in[4];
    const float* Wk     = (const float*)d_in[5];
    const float* bk     = (const float*)d_in[6];
    const float* Wv     = (const float*)d_in[7];
    const float* bv     = (const float*)d_in[8];
    const float* Wp1    = (const float*)d_in[9];
    const float* bp1    = (const float*)d_in[10];
    const float* gp     = (const float*)d_in[11];
    const float* betap  = (const float*)d_in[12];
    const float* Wp2    = (const float*)d_in[13];
    const float* bp2    = (const float*)d_in[14];
    const float* gw1    = (const float*)d_in[15];
    const float* betaw1 = (const float*)d_in[16];
    const float* Ww1    = (const float*)d_in[17];
    const float* bw1    = (const float*)d_in[18];
    const float* gw2    = (const float*)d_in[19];
    const float* betaw2 = (const float*)d_in[20];
    const float* Ww2    = (const float*)d_in[21];
    const float* bw2    = (const float*)d_in[22];
    float* out = (float*)d_out;

    dim3 ggrid((NPTS + 127) / 128, 3);
    qkv_gemm<<<ggrid, 256>>>(x, Wq, bq, Wk, bk, Wv, bv);

    attn_kernel<<<NPTS, 128>>>(p, idx,
                               Wp1, bp1, gp, betap, Wp2, bp2,
                               gw1, betaw1, Ww1, bw1,
                               gw2, betaw2, Ww2, bw2,
                               out);
}

// round 4
// speedup vs baseline: 1.1476x; 1.1476x over previous
#include <cuda_runtime.h>
#include <cstdint>

#define NPTS 30000
#define CDIM 128
#define HEADS 8
#define DHEAD 16
#define SNBR 16
#define OSDIM 16
#define EPSV 1e-5f

// Scratch (device globals: no allocation allowed)
__device__ float g_xq[NPTS * CDIM];
__device__ float g_xk[NPTS * CDIM];
__device__ float g_xv[NPTS * CDIM];
__device__ float g_rs2[OSDIM];
__device__ float g_bw2sum;

// ---------------------------------------------------------------------------
// Kernel 0: one-time derived constants (rowsum(Ww2), sum(bw2))
// ---------------------------------------------------------------------------
__global__ void prep_kernel(const float* __restrict__ Ww2,
                            const float* __restrict__ bw2)
{
    int t = threadIdx.x;   // 16 threads
    float rs = 0.f;
#pragma unroll
    for (int o = 0; o < OSDIM; o++) rs += Ww2[t * OSDIM + o];
    g_rs2[t] = rs;
    if (t == 0) {
        float sb = 0.f;
#pragma unroll
        for (int o = 0; o < OSDIM; o++) sb += bw2[o];
        g_bw2sum = sb;
    }
}

// ---------------------------------------------------------------------------
// Kernel 1: fused QKV GEMM.  grid = (ceil(N/128), 3), block = 256.
// 128x128 output tile per block, 8x8 micro-tile per thread, K-step 8.
// (~88% of SIMT FFMA roofline; unchanged this round)
// ---------------------------------------------------------------------------
__global__ __launch_bounds__(256, 2)
void qkv_gemm(const float* __restrict__ x,
              const float* __restrict__ Wq, const float* __restrict__ bq,
              const float* __restrict__ Wk, const float* __restrict__ bk,
              const float* __restrict__ Wv, const float* __restrict__ bv)
{
    const float* W;
    const float* bias;
    float* dst;
    if (blockIdx.y == 0)      { W = Wq; bias = bq; dst = g_xq; }
    else if (blockIdx.y == 1) { W = Wk; bias = bk; dst = g_xk; }
    else                      { W = Wv; bias = bv; dst = g_xv; }

    __shared__ __align__(16) float As[8][132];
    __shared__ __align__(16) float Bs[8][132];

    const int t   = threadIdx.x;
    const int tx  = t & 15;
    const int ty  = t >> 4;
    const int row0 = blockIdx.x * 128;

    float acc[8][8];
#pragma unroll
    for (int i = 0; i < 8; i++)
#pragma unroll
        for (int j = 0; j < 8; j++) acc[i][j] = 0.f;

    for (int kk = 0; kk < CDIM; kk += 8) {
#pragma unroll
        for (int r = 0; r < 4; r++) {
            int q = t + r * 256;
            int m = q >> 3;
            int k = q & 7;
            int gr = row0 + m;
            As[k][m] = (gr < NPTS) ? x[gr * CDIM + kk + k] : 0.f;
        }
#pragma unroll
        for (int r = 0; r < 4; r++) {
            int q = t + r * 256;
            int k = q >> 7;
            int n = q & 127;
            Bs[k][n] = W[(kk + k) * CDIM + n];
        }
        __syncthreads();

#pragma unroll
        for (int k = 0; k < 8; k++) {
            float4 a0 = *(const float4*)&As[k][ty * 8];
            float4 a1 = *(const float4*)&As[k][ty * 8 + 4];
            float4 b0 = *(const float4*)&Bs[k][tx * 8];
            float4 b1 = *(const float4*)&Bs[k][tx * 8 + 4];
            float a[8] = {a0.x, a0.y, a0.z, a0.w, a1.x, a1.y, a1.z, a1.w};
            float b[8] = {b0.x, b0.y, b0.z, b0.w, b1.x, b1.y, b1.z, b1.w};
#pragma unroll
            for (int i = 0; i < 8; i++)
#pragma unroll
                for (int j = 0; j < 8; j++)
                    acc[i][j] += a[i] * b[j];
        }
        __syncthreads();
    }

    float bj[8];
#pragma unroll
    for (int j = 0; j < 8; j++) bj[j] = bias[tx * 8 + j];

#pragma unroll
    for (int i = 0; i < 8; i++) {
        int gr = row0 + ty * 8 + i;
        if (gr < NPTS) {
            float4 o0, o1;
            o0.x = acc[i][0] + bj[0]; o0.y = acc[i][1] + bj[1];
            o0.z = acc[i][2] + bj[2]; o0.w = acc[i][3] + bj[3];
            o1.x = acc[i][4] + bj[4]; o1.y = acc[i][5] + bj[5];
            o1.z = acc[i][6] + bj[6]; o1.w = acc[i][7] + bj[7];
            *(float4*)&dst[gr * CDIM + tx * 8]     = o0;
            *(float4*)&dst[gr * CDIM + tx * 8 + 4] = o1;
        }
    }
}

// ---------------------------------------------------------------------------
// Kernel 2: per-point fused attention. One block (128 threads) per point.
// tid = h*16+s. k/v gathered into XOR-swizzled smem (float4, conflict-free).
// Softmax over s = 16-lane shfl butterfly; output via reduce-scatter butterfly
// so lane s holds channel s -> fully coalesced direct store.
// ---------------------------------------------------------------------------
__global__ __launch_bounds__(128)
void attn_kernel(const float* __restrict__ p,
                 const int*   __restrict__ idx,
                 const float* __restrict__ Wp1, const float* __restrict__ bp1,
                 const float* __restrict__ gp,  const float* __restrict__ betap,
                 const float* __restrict__ Wp2, const float* __restrict__ bp2,
                 const float* __restrict__ gw1, const float* __restrict__ betaw1,
                 const float* __restrict__ Ww1, const float* __restrict__ bw1,
                 const float* __restrict__ gw2, const float* __restrict__ betaw2,
                 float* __restrict__ out)
{
    const int i   = blockIdx.x;
    const int tid = threadIdx.x;          // 0..127

    __shared__ __align__(16) float skv[2 * SNBR * CDIM];  // [0..2047]=K, [2048..]=V
    __shared__ __align__(16) float swp2[3 * CDIM];
    __shared__ __align__(16) float sbp2[CDIM];
    __shared__ __align__(16) float sW1[DHEAD * OSDIM];
    __shared__ __align__(16) float sgw1[DHEAD], sbetaw1[DHEAD];
    __shared__ __align__(16) float sgw2[OSDIM], sbetaw2[OSDIM];
    __shared__ __align__(16) float sbw1[OSDIM], srs2[OSDIM];
    __shared__ float sbw2sum;
    __shared__ int   sidx[SNBR];

    // --- stage block-constant data (one LDG+STS each; hot reads are LDS bcast) ---
    if (tid < SNBR) {
        sidx[tid]    = idx[i * SNBR + tid];
        sgw1[tid]    = gw1[tid];
        sbetaw1[tid] = betaw1[tid];
        sgw2[tid]    = gw2[tid];
        sbetaw2[tid] = betaw2[tid];
        sbw1[tid]    = bw1[tid];
        srs2[tid]    = g_rs2[tid];
    }
    if (tid == 0) sbw2sum = g_bw2sum;
    swp2[tid]       = Wp2[tid];
    swp2[128 + tid] = Wp2[128 + tid];
    swp2[256 + tid] = Wp2[256 + tid];
    sbp2[tid]       = bp2[tid];
    sW1[tid]        = Ww1[tid];
    sW1[128 + tid]  = Ww1[128 + tid];
    __syncthreads();

    // --- gather k/v rows: coalesced float4 LDG -> XOR-swizzled float4 STS ---
    {
        const int warp = tid >> 5;
        const int lane = tid & 31;
#pragma unroll
        for (int j = 0; j < 4; j++) {
            int sr  = warp * 4 + j;
            int row = sidx[sr];
            float4 k4 = __ldg((const float4*)(g_xk + (size_t)row * CDIM) + lane);
            float4 v4 = __ldg((const float4*)(g_xv + (size_t)row * CDIM) + lane);
            int g = lane ^ (sr & 7);
            *(float4*)&skv[sr * CDIM + g * 4]                     = k4;
            *(float4*)&skv[SNBR * CDIM + sr * CDIM + g * 4]       = v4;
        }
    }
    __syncthreads();

    const int s    = tid & 15;      // neighbor
    const int h    = tid >> 4;      // head
    const int base = h * DHEAD;

    // --- positional encoding front-end for (i, s) ---
    const int nrow = sidx[s];
    float pr0 = p[nrow * 3 + 0] - p[i * 3 + 0];
    float pr1 = p[nrow * 3 + 1] - p[i * 3 + 1];
    float pr2 = p[nrow * 3 + 2] - p[i * 3 + 2];

    float t0 = pr0 * Wp1[0] + pr1 * Wp1[3] + pr2 * Wp1[6] + bp1[0];
    float t1 = pr0 * Wp1[1] + pr1 * Wp1[4] + pr2 * Wp1[7] + bp1[1];
    float t2 = pr0 * Wp1[2] + pr1 * Wp1[5] + pr2 * Wp1[8] + bp1[2];

    float m3 = (t0 + t1 + t2) * (1.f / 3.f);
    float d0 = t0 - m3, d1 = t1 - m3, d2 = t2 - m3;
    float v3 = (d0 * d0 + d1 * d1 + d2 * d2) * (1.f / 3.f);
    float rstd3 = rsqrtf(v3 + EPSV);
    float a0 = fmaxf(d0 * rstd3 * gp[0] + betap[0], 0.f);
    float a1 = fmaxf(d1 * rstd3 * gp[1] + betap[1], 0.f);
    float a2 = fmaxf(d2 * rstd3 * gp[2] + betap[2], 0.f);

    // --- r = k + pe - q ;  ve = v + pe   (all float4 traffic) ---
    float r[DHEAD], ve[DHEAD];
    const float4* xq4 = (const float4*)(g_xq + (size_t)i * CDIM + base);
#pragma unroll
    for (int j = 0; j < 4; j++) {
        int g = ((h << 2) + j) ^ (s & 7);
        float4 kk = *(const float4*)&skv[s * CDIM + g * 4];
        float4 vv = *(const float4*)&skv[SNBR * CDIM + s * CDIM + g * 4];
        float4 w0 = *(const float4*)&swp2[base + j * 4];
        float4 w1r = *(const float4*)&swp2[128 + base + j * 4];
        float4 w2r = *(const float4*)&swp2[256 + base + j * 4];
        float4 bb = *(const float4*)&sbp2[base + j * 4];
        float4 qq = __ldg(xq4 + j);

        float pe0 = fmaf(a0, w0.x, fmaf(a1, w1r.x, fmaf(a2, w2r.x, bb.x)));
        float pe1 = fmaf(a0, w0.y, fmaf(a1, w1r.y, fmaf(a2, w2r.y, bb.y)));
        float pe2 = fmaf(a0, w0.z, fmaf(a1, w1r.z, fmaf(a2, w2r.z, bb.z)));
        float pe3 = fmaf(a0, w0.w, fmaf(a1, w1r.w, fmaf(a2, w2r.w, bb.w)));

        r[j * 4 + 0] = kk.x + pe0 - qq.x;  ve[j * 4 + 0] = vv.x + pe0;
        r[j * 4 + 1] = kk.y + pe1 - qq.y;  ve[j * 4 + 1] = vv.y + pe1;
        r[j * 4 + 2] = kk.z + pe2 - qq.z;  ve[j * 4 + 2] = vv.z + pe2;
        r[j * 4 + 3] = kk.w + pe3 - qq.w;  ve[j * 4 + 3] = vv.w + pe3;
    }

    // --- LN over D, relu ---
    {
        float mean = 0.f;
#pragma unroll
        for (int d = 0; d < DHEAD; d++) mean += r[d];
        mean *= (1.f / DHEAD);
        float var = 0.f;
#pragma unroll
        for (int d = 0; d < DHEAD; d++) { float dd = r[d] - mean; var = fmaf(dd, dd, var); }
        var *= (1.f / DHEAD);
        float rstd = rsqrtf(var + EPSV);
#pragma unroll
        for (int j = 0; j < 4; j++) {
            float4 gg = *(const float4*)&sgw1[j * 4];
            float4 bb = *(const float4*)&sbetaw1[j * 4];
            r[j * 4 + 0] = fmaxf((r[j * 4 + 0] - mean) * rstd * gg.x + bb.x, 0.f);
            r[j * 4 + 1] = fmaxf((r[j * 4 + 1] - mean) * rstd * gg.y + bb.y, 0.f);
            r[j * 4 + 2] = fmaxf((r[j * 4 + 2] - mean) * rstd * gg.z + bb.z, 0.f);
            r[j * 4 + 3] = fmaxf((r[j * 4 + 3] - mean) * rstd * gg.w + bb.w, 0.f);
        }
    }

    // --- w1 = relu_ln(r) @ Ww1 + bw1  (sW1 reads are warp-uniform broadcasts) ---
    float w1[OSDIM];
#pragma unroll
    for (int j = 0; j < 4; j++) {
        float4 bb = *(const float4*)&sbw1[j * 4];
        w1[j * 4 + 0] = bb.x; w1[j * 4 + 1] = bb.y;
        w1[j * 4 + 2] = bb.z; w1[j * 4 + 3] = bb.w;
    }
#pragma unroll
    for (int d = 0; d < DHEAD; d++) {
        float ud = r[d];
#pragma unroll
        for (int o4 = 0; o4 < OSDIM; o4 += 4) {
            float4 wv = *(const float4*)&sW1[d * OSDIM + o4];
            w1[o4 + 0] = fmaf(ud, wv.x, w1[o4 + 0]);
            w1[o4 + 1] = fmaf(ud, wv.y, w1[o4 + 1]);
            w1[o4 + 2] = fmaf(ud, wv.z, w1[o4 + 2]);
            w1[o4 + 3] = fmaf(ud, wv.w, w1[o4 + 3]);
        }
    }

    // --- LN over OS, relu ---
    {
        float mean = 0.f;
#pragma unroll
        for (int o = 0; o < OSDIM; o++) mean += w1[o];
        mean *= (1.f / OSDIM);
        float var = 0.f;
#pragma unroll
        for (int o = 0; o < OSDIM; o++) { float dd = w1[o] - mean; var = fmaf(dd, dd, var); }
        var *= (1.f / OSDIM);
        float rstd = rsqrtf(var + EPSV);
#pragma unroll
        for (int j = 0; j < 4; j++) {
            float4 gg = *(const float4*)&sgw2[j * 4];
            float4 bb = *(const float4*)&sbetaw2[j * 4];
            w1[j * 4 + 0] = fmaxf((w1[j * 4 + 0] - mean) * rstd * gg.x + bb.x, 0.f);
            w1[j * 4 + 1] = fmaxf((w1[j * 4 + 1] - mean) * rstd * gg.y + bb.y, 0.f);
            w1[j * 4 + 2] = fmaxf((w1[j * 4 + 2] - mean) * rstd * gg.z + bb.z, 0.f);
            w1[j * 4 + 3] = fmaxf((w1[j * 4 + 3] - mean) * rstd * gg.w + bb.w, 0.f);
        }
    }

    // --- logit = mean_o(y @ Ww2 + bw2) = y @ rowsum(Ww2)/16 + mean(bw2) ---
    float logit = sbw2sum;
#pragma unroll
    for (int j = 0; j < 4; j++) {
        float4 rr = *(const float4*)&srs2[j * 4];
        logit = fmaf(w1[j * 4 + 0], rr.x, logit);
        logit = fmaf(w1[j * 4 + 1], rr.y, logit);
        logit = fmaf(w1[j * 4 + 2], rr.z, logit);
        logit = fmaf(w1[j * 4 + 3], rr.w, logit);
    }
    logit *= (1.f / OSDIM);

    // --- softmax over s (16-lane butterfly inside half-warp) ---
    float mx = logit;
#pragma unroll
    for (int j = 8; j >= 1; j >>= 1)
        mx = fmaxf(mx, __shfl_xor_sync(0xffffffffu, mx, j));
    float e = __expf(logit - mx);
    float se = e;
#pragma unroll
    for (int j = 8; j >= 1; j >>= 1)
        se += __shfl_xor_sync(0xffffffffu, se, j);
    float w = __fdividef(e, se);

    // --- weighted reduce-scatter butterfly over s: 15 shfl, lane s ends with
    //     output channel s of its head -> coalesced direct store ---
#pragma unroll
    for (int d = 0; d < DHEAD; d++) ve[d] *= w;
#pragma unroll
    for (int m = 8; m >= 1; m >>= 1) {
        bool up = (s & m) != 0;
#pragma unroll
        for (int d = 0; d < m; d++) {
            float send = up ? ve[d] : ve[d + m];
            float recv = __shfl_xor_sync(0xffffffffu, send, m);
            float keep = up ? ve[d + m] : ve[d];
            ve[d] = keep + recv;
        }
    }

    out[(size_t)i * CDIM + tid] = ve[0];
}

// ---------------------------------------------------------------------------
// Launch
// ---------------------------------------------------------------------------
extern "C" void kernel_launch(void* const* d_in, const int* in_sizes, int n_in,
                              void* d_out, int out_size)
{
    const float* p      = (const float*)d_in[0];
    const float* x      = (const float*)d_in[1];
    const int*   idx    = (const int*)  d_in[2];
    const float* Wq     = (const float*)d_in[3];
    const float* bq     = (const float*)d_in[4];
    const float* Wk     = (const float*)d_in[5];
    const float* bk     = (const float*)d_in[6];
    const float* Wv     = (const float*)d_in[7];
    const float* bv     = (const float*)d_in[8];
    const float* Wp1    = (const float*)d_in[9];
    const float* bp1    = (const float*)d_in[10];
    const float* gp     = (const float*)d_in[11];
    const float* betap  = (const float*)d_in[12];
    const float* Wp2    = (const float*)d_in[13];
    const float* bp2    = (const float*)d_in[14];
    const float* gw1    = (const float*)d_in[15];
    const float* betaw1 = (const float*)d_in[16];
    const float* Ww1    = (const float*)d_in[17];
    const float* bw1    = (const float*)d_in[18];
    const float* gw2    = (const float*)d_in[19];
    const float* betaw2 = (const float*)d_in[20];
    const float* Ww2    = (const float*)d_in[21];
    const float* bw2    = (const float*)d_in[22];
    float* out = (float*)d_out;

    prep_kernel<<<1, 16>>>(Ww2, bw2);

    dim3 ggrid((NPTS + 127) / 128, 3);
    qkv_gemm<<<ggrid, 256>>>(x, Wq, bq, Wk, bk, Wv, bv);

    attn_kernel<<<NPTS, 128>>>(p, idx,
                               Wp1, bp1, gp, betap, Wp2, bp2,
                               gw1, betaw1, Ww1, bw1,
                               gw2, betaw2,
                               out);
}

// round 5
// speedup vs baseline: 1.2382x; 1.0789x over previous
#include <cuda_runtime.h>
#include <cstdint>

#define NPTS 30000
#define CDIM 128
#define HEADS 8
#define DHEAD 16
#define SNBR 16
#define OSDIM 16
#define EPSV 1e-5f

typedef unsigned long long u64;

// packed f32x2 helpers (FFMA2 path — PTX-only on sm_103a)
#define F32X2_FMA(d, a, b, c) \
    asm("fma.rn.f32x2 %0, %1, %2, %3;" : "=l"(d) : "l"(a), "l"(b), "l"(c))
#define F32X2_ADD(d, a, b) \
    asm("add.rn.f32x2 %0, %1, %2;" : "=l"(d) : "l"(a), "l"(b))
#define F32X2_MUL(d, a, b) \
    asm("mul.rn.f32x2 %0, %1, %2;" : "=l"(d) : "l"(a), "l"(b))

__device__ __forceinline__ u64 pack2(float lo, float hi) {
    u64 r; asm("mov.b64 %0, {%1, %2};" : "=l"(r) : "f"(lo), "f"(hi)); return r;
}
__device__ __forceinline__ u64 dup2(float x) {
    u64 r; asm("mov.b64 %0, {%1, %1};" : "=l"(r) : "f"(x)); return r;
}
__device__ __forceinline__ float2 unpack2(u64 v) {
    float lo, hi; asm("mov.b64 {%0, %1}, %2;" : "=f"(lo), "=f"(hi) : "l"(v));
    return make_float2(lo, hi);
}
__device__ __forceinline__ u64 relu2(u64 x) {
    float2 f = unpack2(x);
    return pack2(fmaxf(f.x, 0.f), fmaxf(f.y, 0.f));
}

#define NEG1P 0xBF800000BF800000ULL   // (-1.0f, -1.0f)

// Scratch (device globals: no allocation allowed)
__device__ __align__(256) float g_xq[NPTS * CDIM];
__device__ __align__(256) float g_xk[NPTS * CDIM];
__device__ __align__(256) float g_xv[NPTS * CDIM];

// ---------------------------------------------------------------------------
// Kernel 1: fused QKV GEMM, f32x2-packed mainloop.
// grid = (ceil(N/128), 3), block = 256. 128x128 tile, 8x8 micro-tile.
// ---------------------------------------------------------------------------
__global__ __launch_bounds__(256, 2)
void qkv_gemm(const float* __restrict__ x,
              const float* __restrict__ Wq, const float* __restrict__ bq,
              const float* __restrict__ Wk, const float* __restrict__ bk,
              const float* __restrict__ Wv, const float* __restrict__ bv)
{
    const float* W;
    const float* bias;
    float* dst;
    if (blockIdx.y == 0)      { W = Wq; bias = bq; dst = g_xq; }
    else if (blockIdx.y == 1) { W = Wk; bias = bk; dst = g_xk; }
    else                      { W = Wv; bias = bv; dst = g_xv; }

    __shared__ __align__(16) float As[8][132];
    __shared__ __align__(16) float Bs[8][132];

    const int t   = threadIdx.x;
    const int tx  = t & 15;
    const int ty  = t >> 4;
    const int row0 = blockIdx.x * 128;

    u64 accp[8][4];   // [i][j-pair], each u64 = (acc[i][2j], acc[i][2j+1])
#pragma unroll
    for (int i = 0; i < 8; i++)
#pragma unroll
        for (int j = 0; j < 4; j++) accp[i][j] = 0ULL;

    for (int kk = 0; kk < CDIM; kk += 8) {
#pragma unroll
        for (int r = 0; r < 4; r++) {
            int q = t + r * 256;
            int m = q >> 3;
            int k = q & 7;
            int gr = row0 + m;
            As[k][m] = (gr < NPTS) ? x[gr * CDIM + kk + k] : 0.f;
        }
#pragma unroll
        for (int r = 0; r < 4; r++) {
            int q = t + r * 256;
            int k = q >> 7;
            int n = q & 127;
            Bs[k][n] = W[(kk + k) * CDIM + n];
        }
        __syncthreads();

#pragma unroll
        for (int k = 0; k < 8; k++) {
            float4 a0 = *(const float4*)&As[k][ty * 8];
            float4 a1 = *(const float4*)&As[k][ty * 8 + 4];
            ulonglong2 b0 = *(const ulonglong2*)&Bs[k][tx * 8];
            ulonglong2 b1 = *(const ulonglong2*)&Bs[k][tx * 8 + 4];
            u64 bp0 = b0.x, bp1 = b0.y, bp2 = b1.x, bp3 = b1.y;
            float a[8] = {a0.x, a0.y, a0.z, a0.w, a1.x, a1.y, a1.z, a1.w};
#pragma unroll
            for (int i = 0; i < 8; i++) {
                u64 ad = dup2(a[i]);
                F32X2_FMA(accp[i][0], ad, bp0, accp[i][0]);
                F32X2_FMA(accp[i][1], ad, bp1, accp[i][1]);
                F32X2_FMA(accp[i][2], ad, bp2, accp[i][2]);
                F32X2_FMA(accp[i][3], ad, bp3, accp[i][3]);
            }
        }
        __syncthreads();
    }

    // Epilogue: packed bias add, packed store.
    ulonglong2 bb0 = *(const ulonglong2*)&bias[tx * 8];
    ulonglong2 bb1 = *(const ulonglong2*)&bias[tx * 8 + 4];
    u64 bjp[4] = {bb0.x, bb0.y, bb1.x, bb1.y};

#pragma unroll
    for (int i = 0; i < 8; i++) {
        int gr = row0 + ty * 8 + i;
        if (gr < NPTS) {
            u64 o0, o1, o2, o3;
            F32X2_ADD(o0, accp[i][0], bjp[0]);
            F32X2_ADD(o1, accp[i][1], bjp[1]);
            F32X2_ADD(o2, accp[i][2], bjp[2]);
            F32X2_ADD(o3, accp[i][3], bjp[3]);
            ulonglong2 s0, s1;
            s0.x = o0; s0.y = o1; s1.x = o2; s1.y = o3;
            *(ulonglong2*)&dst[gr * CDIM + tx * 8]     = s0;
            *(ulonglong2*)&dst[gr * CDIM + tx * 8 + 4] = s1;
        }
    }
}

// ---------------------------------------------------------------------------
// Kernel 2: per-point fused attention, f32x2-packed core.
// One block (128 threads) per point; tid = h*16+s.
// ---------------------------------------------------------------------------
__global__ __launch_bounds__(128)
void attn_kernel(const float* __restrict__ p,
                 const int*   __restrict__ idx,
                 const float* __restrict__ Wp1, const float* __restrict__ bp1,
                 const float* __restrict__ gp,  const float* __restrict__ betap,
                 const float* __restrict__ Wp2, const float* __restrict__ bp2,
                 const float* __restrict__ gw1, const float* __restrict__ betaw1,
                 const float* __restrict__ Ww1, const float* __restrict__ bw1,
                 const float* __restrict__ gw2, const float* __restrict__ betaw2,
                 const float* __restrict__ Ww2, const float* __restrict__ bw2,
                 float* __restrict__ out)
{
    const int i   = blockIdx.x;
    const int tid = threadIdx.x;          // 0..127

    __shared__ __align__(16) float skv[2 * SNBR * CDIM];  // K then V, swizzled
    __shared__ __align__(16) float sve[128 * 20];         // per-thread ve stash
    __shared__ __align__(16) float swp2[3 * CDIM];
    __shared__ __align__(16) float sbp2[CDIM];
    __shared__ __align__(16) float sW1[DHEAD * OSDIM];
    __shared__ __align__(16) float sgw1[DHEAD], sbetaw1[DHEAD];
    __shared__ __align__(16) float sgw2[OSDIM], sbetaw2[OSDIM];
    __shared__ __align__(16) float sbw1[OSDIM], srs2[OSDIM];
    __shared__ float sbw2sum;
    __shared__ int   sidx[SNBR];

    // --- stage block-constant data ---
    if (tid < SNBR) {
        sidx[tid]    = idx[i * SNBR + tid];
        sgw1[tid]    = gw1[tid];
        sbetaw1[tid] = betaw1[tid];
        sgw2[tid]    = gw2[tid];
        sbetaw2[tid] = betaw2[tid];
        sbw1[tid]    = bw1[tid];
        // rowsum(Ww2) computed in-block (prep kernel folded in)
        const float4* w2r = (const float4*)(Ww2 + tid * OSDIM);
        float4 r0 = __ldg(w2r),     r1 = __ldg(w2r + 1);
        float4 r2 = __ldg(w2r + 2), r3 = __ldg(w2r + 3);
        srs2[tid] = (r0.x + r0.y + r0.z + r0.w) + (r1.x + r1.y + r1.z + r1.w)
                  + (r2.x + r2.y + r2.z + r2.w) + (r3.x + r3.y + r3.z + r3.w);
    }
    if (tid == 0) {
        const float4* b2 = (const float4*)bw2;
        float4 r0 = __ldg(b2), r1 = __ldg(b2 + 1);
        float4 r2 = __ldg(b2 + 2), r3 = __ldg(b2 + 3);
        sbw2sum = (r0.x + r0.y + r0.z + r0.w) + (r1.x + r1.y + r1.z + r1.w)
                + (r2.x + r2.y + r2.z + r2.w) + (r3.x + r3.y + r3.z + r3.w);
    }
    swp2[tid]       = Wp2[tid];
    swp2[128 + tid] = Wp2[128 + tid];
    swp2[256 + tid] = Wp2[256 + tid];
    sbp2[tid]       = bp2[tid];
    sW1[tid]        = Ww1[tid];
    sW1[128 + tid]  = Ww1[128 + tid];
    __syncthreads();

    // --- gather k/v rows: coalesced float4 LDG -> XOR-swizzled float4 STS ---
    {
        const int warp = tid >> 5;
        const int lane = tid & 31;
#pragma unroll
        for (int j = 0; j < 4; j++) {
            int sr  = warp * 4 + j;
            int row = sidx[sr];
            float4 k4 = __ldg((const float4*)(g_xk + (size_t)row * CDIM) + lane);
            float4 v4 = __ldg((const float4*)(g_xv + (size_t)row * CDIM) + lane);
            int g = lane ^ (sr & 7);
            *(float4*)&skv[sr * CDIM + g * 4]               = k4;
            *(float4*)&skv[SNBR * CDIM + sr * CDIM + g * 4] = v4;
        }
    }
    __syncthreads();

    const int s    = tid & 15;      // neighbor
    const int h    = tid >> 4;      // head
    const int base = h * DHEAD;

    // --- positional encoding front-end (scalar, tiny) ---
    const int nrow = sidx[s];
    float pr0 = p[nrow * 3 + 0] - p[i * 3 + 0];
    float pr1 = p[nrow * 3 + 1] - p[i * 3 + 1];
    float pr2 = p[nrow * 3 + 2] - p[i * 3 + 2];

    float t0 = pr0 * Wp1[0] + pr1 * Wp1[3] + pr2 * Wp1[6] + bp1[0];
    float t1 = pr0 * Wp1[1] + pr1 * Wp1[4] + pr2 * Wp1[7] + bp1[1];
    float t2 = pr0 * Wp1[2] + pr1 * Wp1[5] + pr2 * Wp1[8] + bp1[2];

    float m3 = (t0 + t1 + t2) * (1.f / 3.f);
    float d0 = t0 - m3, d1 = t1 - m3, d2 = t2 - m3;
    float v3 = (d0 * d0 + d1 * d1 + d2 * d2) * (1.f / 3.f);
    float rstd3 = rsqrtf(v3 + EPSV);
    float a0 = fmaxf(d0 * rstd3 * gp[0] + betap[0], 0.f);
    float a1 = fmaxf(d1 * rstd3 * gp[1] + betap[1], 0.f);
    float a2 = fmaxf(d2 * rstd3 * gp[2] + betap[2], 0.f);

    const u64 a0d = dup2(a0), a1d = dup2(a1), a2d = dup2(a2);
    const u64 neg1 = NEG1P;

    // --- r = k + pe - q ; ve = v + pe (packed). ve stashed to smem. ---
    u64 rp[8];
    const ulonglong2* xq2 = (const ulonglong2*)(g_xq + (size_t)i * CDIM + base);
#pragma unroll
    for (int j = 0; j < 4; j++) {
        int g = ((h << 2) + j) ^ (s & 7);
        ulonglong2 kk = *(const ulonglong2*)&skv[s * CDIM + g * 4];
        ulonglong2 vv = *(const ulonglong2*)&skv[SNBR * CDIM + s * CDIM + g * 4];
        ulonglong2 w0 = *(const ulonglong2*)&swp2[base + j * 4];
        ulonglong2 w1 = *(const ulonglong2*)&swp2[128 + base + j * 4];
        ulonglong2 w2 = *(const ulonglong2*)&swp2[256 + base + j * 4];
        ulonglong2 bb = *(const ulonglong2*)&sbp2[base + j * 4];
        ulonglong2 qq = __ldg(xq2 + j);

        u64 pe0, pe1, tmp;
        F32X2_FMA(tmp, a2d, w2.x, bb.x);
        F32X2_FMA(tmp, a1d, w1.x, tmp);
        F32X2_FMA(pe0, a0d, w0.x, tmp);
        F32X2_FMA(tmp, a2d, w2.y, bb.y);
        F32X2_FMA(tmp, a1d, w1.y, tmp);
        F32X2_FMA(pe1, a0d, w0.y, tmp);

        u64 r0, r1;
        F32X2_ADD(r0, kk.x, pe0);
        F32X2_FMA(r0, qq.x, neg1, r0);
        F32X2_ADD(r1, kk.y, pe1);
        F32X2_FMA(r1, qq.y, neg1, r1);
        rp[j * 2 + 0] = r0;
        rp[j * 2 + 1] = r1;

        ulonglong2 vs;
        F32X2_ADD(vs.x, vv.x, pe0);
        F32X2_ADD(vs.y, vv.y, pe1);
        *(ulonglong2*)&sve[tid * 20 + j * 4] = vs;   // stride-20 pad: conflict-free
    }

    // --- LN over D (packed stats), relu -> scalar r[16] ---
    float r[DHEAD];
    {
        u64 sp = rp[0];
        F32X2_ADD(sp, sp, rp[1]); F32X2_ADD(sp, sp, rp[2]); F32X2_ADD(sp, sp, rp[3]);
        F32X2_ADD(sp, sp, rp[4]); F32X2_ADD(sp, sp, rp[5]); F32X2_ADD(sp, sp, rp[6]);
        F32X2_ADD(sp, sp, rp[7]);
        float2 sf = unpack2(sp);
        float mean = (sf.x + sf.y) * (1.f / DHEAD);
        u64 meanp = dup2(mean);
        u64 vp = 0ULL;
#pragma unroll
        for (int j = 0; j < 8; j++) {
            u64 dd;
            F32X2_FMA(dd, meanp, neg1, rp[j]);   // dd = r - mean
            F32X2_FMA(vp, dd, dd, vp);
            rp[j] = dd;
        }
        float2 vf = unpack2(vp);
        float rstd = rsqrtf((vf.x + vf.y) * (1.f / DHEAD) + EPSV);
        u64 rstdp = dup2(rstd);
        const u64* gwp = (const u64*)sgw1;
        const u64* bwp = (const u64*)sbetaw1;
#pragma unroll
        for (int j = 0; j < 8; j++) {
            u64 rg, t;
            F32X2_MUL(rg, rstdp, gwp[j]);
            F32X2_FMA(t, rp[j], rg, bwp[j]);
            float2 tf = unpack2(t);
            r[2 * j + 0] = fmaxf(tf.x, 0.f);
            r[2 * j + 1] = fmaxf(tf.y, 0.f);
        }
    }

    // --- w1 = relu_ln(r) @ Ww1 + bw1 (packed accumulators) ---
    u64 w1p[8];
    {
        const u64* bw = (const u64*)sbw1;
#pragma unroll
        for (int j = 0; j < 8; j++) w1p[j] = bw[j];
#pragma unroll
        for (int d = 0; d < DHEAD; d++) {
            u64 ud = dup2(r[d]);
            const ulonglong2* wr = (const ulonglong2*)&sW1[d * OSDIM];
            ulonglong2 wa = wr[0], wb = wr[1], wc = wr[2], wd_ = wr[3];
            F32X2_FMA(w1p[0], ud, wa.x, w1p[0]);
            F32X2_FMA(w1p[1], ud, wa.y, w1p[1]);
            F32X2_FMA(w1p[2], ud, wb.x, w1p[2]);
            F32X2_FMA(w1p[3], ud, wb.y, w1p[3]);
            F32X2_FMA(w1p[4], ud, wc.x, w1p[4]);
            F32X2_FMA(w1p[5], ud, wc.y, w1p[5]);
            F32X2_FMA(w1p[6], ud, wd_.x, w1p[6]);
            F32X2_FMA(w1p[7], ud, wd_.y, w1p[7]);
        }
    }

    // --- LN over OS (packed), relu (packed via scalar max) ---
    {
        u64 sp = w1p[0];
        F32X2_ADD(sp, sp, w1p[1]); F32X2_ADD(sp, sp, w1p[2]); F32X2_ADD(sp, sp, w1p[3]);
        F32X2_ADD(sp, sp, w1p[4]); F32X2_ADD(sp, sp, w1p[5]); F32X2_ADD(sp, sp, w1p[6]);
        F32X2_ADD(sp, sp, w1p[7]);
        float2 sf = unpack2(sp);
        float mean = (sf.x + sf.y) * (1.f / OSDIM);
        u64 meanp = dup2(mean);
        u64 vp = 0ULL;
#pragma unroll
        for (int j = 0; j < 8; j++) {
            u64 dd;
            F32X2_FMA(dd, meanp, neg1, w1p[j]);
            F32X2_FMA(vp, dd, dd, vp);
            w1p[j] = dd;
        }
        float2 vf = unpack2(vp);
        float rstd = rsqrtf((vf.x + vf.y) * (1.f / OSDIM) + EPSV);
        u64 rstdp = dup2(rstd);
        const u64* gwp = (const u64*)sgw2;
        const u64* bwp = (const u64*)sbetaw2;
#pragma unroll
        for (int j = 0; j < 8; j++) {
            u64 rg, t;
            F32X2_MUL(rg, rstdp, gwp[j]);
            F32X2_FMA(t, w1p[j], rg, bwp[j]);
            w1p[j] = relu2(t);
        }
    }

    // --- logit = (y @ rowsum(Ww2) + sum(bw2)) / 16 ---
    float logit;
    {
        const u64* rsp = (const u64*)srs2;
        u64 acc = 0ULL;
#pragma unroll
        for (int j = 0; j < 8; j++) F32X2_FMA(acc, w1p[j], rsp[j], acc);
        float2 af = unpack2(acc);
        logit = (af.x + af.y + sbw2sum) * (1.f / OSDIM);
    }

    // --- softmax over s (16-lane butterfly) ---
    float mx = logit;
#pragma unroll
    for (int j = 8; j >= 1; j >>= 1)
        mx = fmaxf(mx, __shfl_xor_sync(0xffffffffu, mx, j));
    float e = __expf(logit - mx);
    float se = e;
#pragma unroll
    for (int j = 8; j >= 1; j >>= 1)
        se += __shfl_xor_sync(0xffffffffu, se, j);
    float w = __fdividef(e, se);

    // --- reload ve, scale, weighted reduce-scatter butterfly ---
    float ve[DHEAD];
#pragma unroll
    for (int j = 0; j < 4; j++) {
        float4 f = *(const float4*)&sve[tid * 20 + j * 4];
        ve[j * 4 + 0] = f.x * w; ve[j * 4 + 1] = f.y * w;
        ve[j * 4 + 2] = f.z * w; ve[j * 4 + 3] = f.w * w;
    }
#pragma unroll
    for (int m = 8; m >= 1; m >>= 1) {
        bool up = (s & m) != 0;
#pragma unroll
        for (int d = 0; d < m; d++) {
            float send = up ? ve[d] : ve[d + m];
            float recv = __shfl_xor_sync(0xffffffffu, send, m);
            float keep = up ? ve[d + m] : ve[d];
            ve[d] = keep + recv;
        }
    }

    out[(size_t)i * CDIM + tid] = ve[0];
}

// ---------------------------------------------------------------------------
// Launch
// ---------------------------------------------------------------------------
extern "C" void kernel_launch(void* const* d_in, const int* in_sizes, int n_in,
                              void* d_out, int out_size)
{
    const float* p      = (const float*)d_in[0];
    const float* x      = (const float*)d_in[1];
    const int*   idx    = (const int*)  d_in[2];
    const float* Wq     = (const float*)d_in[3];
    const float* bq     = (const float*)d_in[4];
    const float* Wk     = (const float*)d_in[5];
    const float* bk     = (const float*)d_in[6];
    const float* Wv     = (const float*)d_in[7];
    const float* bv     = (const float*)d_in[8];
    const float* Wp1    = (const float*)d_in[9];
    const float* bp1    = (const float*)d_in[10];
    const float* gp     = (const float*)d_in[11];
    const float* betap  = (const float*)d_in[12];
    const float* Wp2    = (const float*)d_in[13];
    const float* bp2    = (const float*)d_in[14];
    const float* gw1    = (const float*)d_in[15];
    const float* betaw1 = (const float*)d_in[16];
    const float* Ww1    = (const float*)d_in[17];
    const float* bw1    = (const float*)d_in[18];
    const float* gw2    = (const float*)d_in[19];
    const float* betaw2 = (const float*)d_in[20];
    const float* Ww2    = (const float*)d_in[21];
    const float* bw2    = (const float*)d_in[22];
    float* out = (float*)d_out;

    dim3 ggrid((NPTS + 127) / 128, 3);
    qkv_gemm<<<ggrid, 256>>>(x, Wq, bq, Wk, bk, Wv, bv);

    attn_kernel<<<NPTS, 128>>>(p, idx,
                               Wp1, bp1, gp, betap, Wp2, bp2,
                               gw1, betaw1, Ww1, bw1,
                               gw2, betaw2, Ww2, bw2,
                               out);
}